// round 1
// baseline (speedup 1.0000x reference)
#include <cuda_runtime.h>
#include <cuda_bf16.h>
#include <math.h>

#define B_ 4
#define N_ 1024
#define HW_ 4096
#define D_ 512
#define H_ 8
#define DK_ 64

// ---------------- scratch buffers (static device globals; no allocation) ----
__device__ float g_Q[B_ * N_ * D_];          // 8 MB
__device__ float g_K[B_ * HW_ * D_];         // 32 MB
__device__ float g_V[B_ * HW_ * D_];         // 32 MB
__device__ float g_ctx[B_ * N_ * D_];        // 8 MB
__device__ unsigned char g_mask[N_ * HW_];   // 4 MB

// ---------------- mask precompute: dist(x_tilde[m], x_hat[n,m]) < 0.1 ------
__global__ void mask_kernel(const float* __restrict__ x_tilde,
                            const float* __restrict__ x_hat,
                            unsigned char* __restrict__ mask) {
    int idx = blockIdx.x * blockDim.x + threadIdx.x;
    if (idx >= N_ * HW_) return;
    int m = idx & (HW_ - 1);
    float dx = x_tilde[m * 2 + 0] - x_hat[(size_t)idx * 2 + 0];
    float dy = x_tilde[m * 2 + 1] - x_hat[(size_t)idx * 2 + 1];
    float d = sqrtf(dx * dx + dy * dy);
    mask[idx] = (d < 0.1f) ? 1 : 0;
}

// ---------------- GEMM: C[M,512] = A[M,512] @ W[512,512]^T + bias ----------
#define GBM 64
#define GBN 64
#define GBK 16
#define GPAD 68

__global__ __launch_bounds__(256) void gemm_abt(const float* __restrict__ A,
                                                const float* __restrict__ W,
                                                const float* __restrict__ bias,
                                                float* __restrict__ C) {
    __shared__ float As[GBK][GPAD];
    __shared__ float Bs[GBK][GPAD];
    int tid = threadIdx.x;
    int tx = tid & 15;
    int ty = tid >> 4;
    int m0 = blockIdx.y * GBM;
    int n0 = blockIdx.x * GBN;

    int lrow = tid >> 2;        // 0..63
    int lcol = (tid & 3) * 4;   // 0,4,8,12

    float acc[4][4];
#pragma unroll
    for (int i = 0; i < 4; i++)
#pragma unroll
        for (int j = 0; j < 4; j++) acc[i][j] = 0.0f;

    for (int k0 = 0; k0 < D_; k0 += GBK) {
        float4 a = *(const float4*)(A + (size_t)(m0 + lrow) * D_ + k0 + lcol);
        float4 w = *(const float4*)(W + (size_t)(n0 + lrow) * D_ + k0 + lcol);
        __syncthreads();
        As[lcol + 0][lrow] = a.x; As[lcol + 1][lrow] = a.y;
        As[lcol + 2][lrow] = a.z; As[lcol + 3][lrow] = a.w;
        Bs[lcol + 0][lrow] = w.x; Bs[lcol + 1][lrow] = w.y;
        Bs[lcol + 2][lrow] = w.z; Bs[lcol + 3][lrow] = w.w;
        __syncthreads();
#pragma unroll
        for (int kk = 0; kk < GBK; kk++) {
            float4 av = *(float4*)&As[kk][ty * 4];
            float4 bv = *(float4*)&Bs[kk][tx * 4];
            float a4[4] = {av.x, av.y, av.z, av.w};
            float b4[4] = {bv.x, bv.y, bv.z, bv.w};
#pragma unroll
            for (int i = 0; i < 4; i++)
#pragma unroll
                for (int j = 0; j < 4; j++) acc[i][j] += a4[i] * b4[j];
        }
    }
#pragma unroll
    for (int i = 0; i < 4; i++) {
        float* crow = C + (size_t)(m0 + ty * 4 + i) * D_ + n0 + tx * 4;
        const float* brow = bias + n0 + tx * 4;
#pragma unroll
        for (int j = 0; j < 4; j++) crow[j] = acc[i][j] + brow[j];
    }
}

// ---------------- fused attention -----------------------------------------
// One block = (b,h, 8-query chunk). Scores for 8 rows x 4096 keys live in smem.
#define R_ 8
#define MC_ 128
#define NTH_ 256
#define KPAD_ 68
#define SCS_ 4100   // padded score row stride (breaks bank aliasing; 16B aligned)

#define ATTN_SMEM_FLOATS (R_ * DK_ + MC_ * KPAD_ + R_ * SCS_)
#define ATTN_SMEM_BYTES (ATTN_SMEM_FLOATS * 4)

__global__ __launch_bounds__(NTH_, 1) void attn_kernel(
    const float* __restrict__ Q, const float* __restrict__ K,
    const float* __restrict__ V, const unsigned char* __restrict__ mask,
    float* __restrict__ attn, float* __restrict__ ctx) {
    extern __shared__ float smem[];
    float* qs = smem;                    // R_*DK_  (reused later as ctx-combine buf)
    float* kb = smem + R_ * DK_;         // MC_*KPAD_ (K, then V staging)
    float* sc = kb + MC_ * KPAD_;        // R_*SCS_

    int tid = threadIdx.x;
    int bh = blockIdx.y;
    int b = bh / H_;
    int h = bh % H_;
    int n0 = blockIdx.x * R_;

    const float* Qb = Q + ((size_t)(b * N_ + n0)) * D_ + h * DK_;
    const float* Kb = K + ((size_t)b * HW_) * D_ + h * DK_;
    const float* Vb = V + ((size_t)b * HW_) * D_ + h * DK_;

    // load q tile (8x64)
    for (int i = tid; i < R_ * DK_ / 4; i += NTH_) {
        int r = i >> 4;
        int k4 = i & 15;
        *(float4*)&qs[r * DK_ + k4 * 4] = *(const float4*)(Qb + (size_t)r * D_ + k4 * 4);
    }

    // ---- pass 1: scores ----
    int m_loc = tid & (MC_ - 1);
    int rr = tid >> 7;  // 0/1 -> rows rr*4 .. rr*4+3
    float4 kreg[16];

    for (int mc = 0; mc < HW_; mc += MC_) {
        __syncthreads();
        for (int i = tid; i < MC_ * DK_ / 4; i += NTH_) {
            int m = i >> 4;
            int k4 = i & 15;
            *(float4*)&kb[m * KPAD_ + k4 * 4] =
                *(const float4*)(Kb + (size_t)(mc + m) * D_ + k4 * 4);
        }
        __syncthreads();
#pragma unroll
        for (int k4 = 0; k4 < 16; k4++) kreg[k4] = *(float4*)&kb[m_loc * KPAD_ + k4 * 4];
        int m = mc + m_loc;
#pragma unroll
        for (int rj = 0; rj < 4; rj++) {
            int r = rr * 4 + rj;
            float s = 0.0f;
#pragma unroll
            for (int k4 = 0; k4 < 16; k4++) {
                float4 qv = *(float4*)&qs[r * DK_ + k4 * 4];
                s += qv.x * kreg[k4].x + qv.y * kreg[k4].y +
                     qv.z * kreg[k4].z + qv.w * kreg[k4].w;
            }
            s *= 0.125f;  // 1/sqrt(64)
            unsigned char mk = mask[(size_t)(n0 + r) * HW_ + m];
            sc[r * SCS_ + m] = mk ? s : -INFINITY;
        }
    }
    __syncthreads();

    // ---- softmax: warp w owns row w ----
    {
        int w = tid >> 5;
        int lane = tid & 31;
        float* row = sc + w * SCS_;
        float mx = -INFINITY;
        for (int m = lane; m < HW_; m += 32) mx = fmaxf(mx, row[m]);
#pragma unroll
        for (int o = 16; o; o >>= 1) mx = fmaxf(mx, __shfl_xor_sync(0xffffffffu, mx, o));
        float sum = 0.0f;
        for (int m = lane; m < HW_; m += 32) {
            float e = __expf(row[m] - mx);
            row[m] = e;
            sum += e;
        }
#pragma unroll
        for (int o = 16; o; o >>= 1) sum += __shfl_xor_sync(0xffffffffu, sum, o);
        float inv = 1.0f / sum;
        float* ga = attn + ((size_t)bh * N_ + n0 + w) * HW_;
        for (int m4 = lane; m4 < HW_ / 4; m4 += 32) {
            float4 e4 = *(float4*)&row[m4 * 4];
            e4.x *= inv; e4.y *= inv; e4.z *= inv; e4.w *= inv;
            *(float4*)&row[m4 * 4] = e4;       // normalized probs back to smem
            *(float4*)(ga + m4 * 4) = e4;      // attn output
        }
    }

    // ---- pass 2: ctx = P @ V ----
    int d4 = tid & 15;
    int r = (tid >> 4) & 7;
    int half = tid >> 7;
    float4 acc = make_float4(0.f, 0.f, 0.f, 0.f);

    for (int mc = 0; mc < HW_; mc += MC_) {
        __syncthreads();
        for (int i = tid; i < MC_ * DK_ / 4; i += NTH_) {
            int m = i >> 4;
            int k4 = i & 15;
            *(float4*)&kb[m * KPAD_ + k4 * 4] =
                *(const float4*)(Vb + (size_t)(mc + m) * D_ + k4 * 4);
        }
        __syncthreads();
        int mbase = half * 64;
#pragma unroll 4
        for (int mm = 0; mm < 64; mm++) {
            int m = mbase + mm;
            float p = sc[r * SCS_ + mc + m];
            float4 v = *(float4*)&kb[m * KPAD_ + d4 * 4];
            acc.x += p * v.x; acc.y += p * v.y;
            acc.z += p * v.z; acc.w += p * v.w;
        }
    }
    // combine halves via qs (q no longer needed)
    __syncthreads();
    if (half == 0) *(float4*)&qs[(r * 16 + d4) * 4] = acc;
    __syncthreads();
    if (half == 1) {
        float4 o = *(float4*)&qs[(r * 16 + d4) * 4];
        o.x += acc.x; o.y += acc.y; o.z += acc.z; o.w += acc.w;
        float* gc = ctx + (size_t)(b * N_ + n0 + r) * D_ + h * DK_ + d4 * 4;
        *(float4*)gc = o;
    }
}

// ---------------- launch ---------------------------------------------------
extern "C" void kernel_launch(void* const* d_in, const int* in_sizes, int n_in,
                              void* d_out, int out_size) {
    const float* query   = (const float*)d_in[0];
    const float* key     = (const float*)d_in[1];
    const float* value   = (const float*)d_in[2];
    const float* x_tilde = (const float*)d_in[3];
    const float* x_hat   = (const float*)d_in[4];
    const float* Wq = (const float*)d_in[5];
    const float* bq = (const float*)d_in[6];
    const float* Wk = (const float*)d_in[7];
    const float* bk = (const float*)d_in[8];
    const float* Wv = (const float*)d_in[9];
    const float* bv = (const float*)d_in[10];
    const float* Wo = (const float*)d_in[11];
    const float* bo = (const float*)d_in[12];

    float* out = (float*)d_out;
    float* attn = out + (size_t)B_ * N_ * D_;

    float *Qp, *Kp, *Vp, *Cp;
    unsigned char* Mp;
    cudaGetSymbolAddress((void**)&Qp, g_Q);
    cudaGetSymbolAddress((void**)&Kp, g_K);
    cudaGetSymbolAddress((void**)&Vp, g_V);
    cudaGetSymbolAddress((void**)&Cp, g_ctx);
    cudaGetSymbolAddress((void**)&Mp, g_mask);

    mask_kernel<<<(N_ * HW_ + 255) / 256, 256>>>(x_tilde, x_hat, Mp);

    gemm_abt<<<dim3(D_ / GBN, (B_ * N_) / GBM), 256>>>(query, Wq, bq, Qp);
    gemm_abt<<<dim3(D_ / GBN, (B_ * HW_) / GBM), 256>>>(key, Wk, bk, Kp);
    gemm_abt<<<dim3(D_ / GBN, (B_ * HW_) / GBM), 256>>>(value, Wv, bv, Vp);

    cudaFuncSetAttribute(attn_kernel, cudaFuncAttributeMaxDynamicSharedMemorySize,
                         ATTN_SMEM_BYTES);
    attn_kernel<<<dim3(N_ / R_, B_ * H_), NTH_, ATTN_SMEM_BYTES>>>(Qp, Kp, Vp, Mp,
                                                                   attn, Cp);

    gemm_abt<<<dim3(D_ / GBN, (B_ * N_) / GBM), 256>>>(Cp, Wo, bo, out);
}

// round 2
// speedup vs baseline: 1.9062x; 1.9062x over previous
#include <cuda_runtime.h>
#include <cuda_bf16.h>
#include <math.h>
#include <stdint.h>

#define B_ 4
#define N_ 1024
#define HW_ 4096
#define D_ 512
#define H_ 8
#define DK_ 64

// ---------------- scratch (static device globals; no allocation) -----------
__device__ float g_Q[B_ * N_ * D_];
__device__ float g_K[B_ * HW_ * D_];
__device__ float g_V[B_ * HW_ * D_];
__device__ float g_ctx[B_ * N_ * D_];
__device__ unsigned char g_mask[N_ * HW_];

// ---------------- helpers --------------------------------------------------
__device__ __forceinline__ uint32_t smem_u32(const void* p) {
    return (uint32_t)__cvta_generic_to_shared(p);
}

__device__ __forceinline__ void ldsm4(uint32_t& r0, uint32_t& r1, uint32_t& r2,
                                      uint32_t& r3, uint32_t a) {
    asm volatile("ldmatrix.sync.aligned.m8n8.x4.shared.b16 {%0,%1,%2,%3},[%4];"
                 : "=r"(r0), "=r"(r1), "=r"(r2), "=r"(r3) : "r"(a));
}
__device__ __forceinline__ void ldsm2(uint32_t& r0, uint32_t& r1, uint32_t a) {
    asm volatile("ldmatrix.sync.aligned.m8n8.x2.shared.b16 {%0,%1},[%2];"
                 : "=r"(r0), "=r"(r1) : "r"(a));
}
__device__ __forceinline__ void ldsm2t(uint32_t& r0, uint32_t& r1, uint32_t a) {
    asm volatile("ldmatrix.sync.aligned.m8n8.x2.trans.shared.b16 {%0,%1},[%2];"
                 : "=r"(r0), "=r"(r1) : "r"(a));
}
__device__ __forceinline__ void mma_bf16(float* c, const uint32_t* a, const uint32_t* b) {
    asm volatile(
        "mma.sync.aligned.m16n8k16.row.col.f32.bf16.bf16.f32 "
        "{%0,%1,%2,%3},{%4,%5,%6,%7},{%8,%9},{%0,%1,%2,%3};"
        : "+f"(c[0]), "+f"(c[1]), "+f"(c[2]), "+f"(c[3])
        : "r"(a[0]), "r"(a[1]), "r"(a[2]), "r"(a[3]), "r"(b[0]), "r"(b[1]));
}

// split fp32 pair into packed bf16 hi and lo words
__device__ __forceinline__ void split2(float x, float y, uint32_t& hi, uint32_t& lo) {
    __nv_bfloat16 hx = __float2bfloat16(x);
    __nv_bfloat16 hy = __float2bfloat16(y);
    __nv_bfloat16 lx = __float2bfloat16(x - __bfloat162float(hx));
    __nv_bfloat16 ly = __float2bfloat16(y - __bfloat162float(hy));
    hi = (uint32_t)__bfloat16_as_ushort(hx) | ((uint32_t)__bfloat16_as_ushort(hy) << 16);
    lo = (uint32_t)__bfloat16_as_ushort(lx) | ((uint32_t)__bfloat16_as_ushort(ly) << 16);
}

// ---------------- mask precompute ------------------------------------------
__global__ void mask_kernel(const float* __restrict__ x_tilde,
                            const float* __restrict__ x_hat,
                            unsigned char* __restrict__ mask) {
    int idx = blockIdx.x * blockDim.x + threadIdx.x;
    if (idx >= N_ * HW_) return;
    int m = idx & (HW_ - 1);
    float dx = x_tilde[m * 2 + 0] - x_hat[(size_t)idx * 2 + 0];
    float dy = x_tilde[m * 2 + 1] - x_hat[(size_t)idx * 2 + 1];
    mask[idx] = (sqrtf(dx * dx + dy * dy) < 0.1f) ? 1 : 0;
}

// ---------------- unified split-bf16 MMA GEMM ------------------------------
// C = alpha * A @ op(B) + bias   (op = B^T if TRB, else B)
// A: [M,K] row-major (lda).  TRB: B [N,K] (ldb). !TRB: B [K,N] (ldb).
// batched via blockIdx.z: z = b*8 + h, offsets via (sXb, sXh).
template <int BM, int BN, int BK, int WM, int WN, bool TRB>
__global__ __launch_bounds__(256, 1) void gemm_mma(
    const float* __restrict__ A, const float* __restrict__ Bm,
    const float* __restrict__ bias, float* __restrict__ C, int K,
    int lda, int ldb, int ldc,
    long sAb, long sAh, long sBb, long sBh, long sCb, long sCh, float alpha) {
    constexpr int SA = BK + 8;
    constexpr int SB = TRB ? (BK + 8) : (BN + 8);
    constexpr int BROWS = TRB ? BN : BK;
    __shared__ __align__(16) __nv_bfloat16 Ah[BM * SA];
    __shared__ __align__(16) __nv_bfloat16 Al[BM * SA];
    __shared__ __align__(16) __nv_bfloat16 Bh[BROWS * SB];
    __shared__ __align__(16) __nv_bfloat16 Bl[BROWS * SB];

    int z = blockIdx.z;
    int zb = z >> 3, zh = z & 7;
    A += zb * sAb + zh * sAh;
    Bm += zb * sBb + zh * sBh;
    C += zb * sCb + zh * sCh;

    int m0 = blockIdx.y * BM;
    int n0 = blockIdx.x * BN;
    int tid = threadIdx.x;
    int lane = tid & 31;
    int wid = tid >> 5;
    constexpr int WNC = BN / WN;
    int wm0 = (wid / WNC) * WM;
    int wn0 = (wid % WNC) * WN;
    constexpr int MT = WM / 16;
    constexpr int NT = WN / 8;

    float acc[MT][NT][4];
#pragma unroll
    for (int i = 0; i < MT; i++)
#pragma unroll
        for (int j = 0; j < NT; j++)
#pragma unroll
            for (int q = 0; q < 4; q++) acc[i][j][q] = 0.0f;

    for (int k0 = 0; k0 < K; k0 += BK) {
        __syncthreads();
        // stage A chunk (BM x BK), fp32 -> bf16 hi/lo
        for (int i = tid; i < BM * (BK / 4); i += 256) {
            int r = i / (BK / 4);
            int c = (i % (BK / 4)) * 4;
            float4 v = *(const float4*)(A + (long)(m0 + r) * lda + k0 + c);
            uint32_t h0, l0, h1, l1;
            split2(v.x, v.y, h0, l0);
            split2(v.z, v.w, h1, l1);
            *(uint2*)&Ah[r * SA + c] = make_uint2(h0, h1);
            *(uint2*)&Al[r * SA + c] = make_uint2(l0, l1);
        }
        // stage B chunk
        if constexpr (TRB) {
            for (int i = tid; i < BN * (BK / 4); i += 256) {
                int r = i / (BK / 4);
                int c = (i % (BK / 4)) * 4;
                float4 v = *(const float4*)(Bm + (long)(n0 + r) * ldb + k0 + c);
                uint32_t h0, l0, h1, l1;
                split2(v.x, v.y, h0, l0);
                split2(v.z, v.w, h1, l1);
                *(uint2*)&Bh[r * SB + c] = make_uint2(h0, h1);
                *(uint2*)&Bl[r * SB + c] = make_uint2(l0, l1);
            }
        } else {
            for (int i = tid; i < BK * (BN / 4); i += 256) {
                int r = i / (BN / 4);
                int c = (i % (BN / 4)) * 4;
                float4 v = *(const float4*)(Bm + (long)(k0 + r) * ldb + n0 + c);
                uint32_t h0, l0, h1, l1;
                split2(v.x, v.y, h0, l0);
                split2(v.z, v.w, h1, l1);
                *(uint2*)&Bh[r * SB + c] = make_uint2(h0, h1);
                *(uint2*)&Bl[r * SB + c] = make_uint2(l0, l1);
            }
        }
        __syncthreads();

#pragma unroll
        for (int ks = 0; ks < BK / 16; ks++) {
            uint32_t af[MT][4], al_[MT][4];
#pragma unroll
            for (int mt = 0; mt < MT; mt++) {
                int row = wm0 + mt * 16 + (lane & 7) + ((lane >> 3) & 1) * 8;
                int col = ks * 16 + (lane >> 4) * 8;
                ldsm4(af[mt][0], af[mt][1], af[mt][2], af[mt][3],
                      smem_u32(&Ah[row * SA + col]));
                ldsm4(al_[mt][0], al_[mt][1], al_[mt][2], al_[mt][3],
                      smem_u32(&Al[row * SA + col]));
            }
            uint32_t bf[NT][2], bl_[NT][2];
#pragma unroll
            for (int nt = 0; nt < NT; nt++) {
                if constexpr (TRB) {
                    int row = wn0 + nt * 8 + (lane & 7);
                    int col = ks * 16 + ((lane >> 3) & 1) * 8;
                    ldsm2(bf[nt][0], bf[nt][1], smem_u32(&Bh[row * SB + col]));
                    ldsm2(bl_[nt][0], bl_[nt][1], smem_u32(&Bl[row * SB + col]));
                } else {
                    int row = ks * 16 + (lane & 7) + ((lane >> 3) & 1) * 8;
                    int col = wn0 + nt * 8;
                    ldsm2t(bf[nt][0], bf[nt][1], smem_u32(&Bh[row * SB + col]));
                    ldsm2t(bl_[nt][0], bl_[nt][1], smem_u32(&Bl[row * SB + col]));
                }
            }
#pragma unroll
            for (int mt = 0; mt < MT; mt++)
#pragma unroll
                for (int nt = 0; nt < NT; nt++) {
                    mma_bf16(acc[mt][nt], af[mt], bf[nt]);    // hi*hi
                    mma_bf16(acc[mt][nt], af[mt], bl_[nt]);   // hi*lo
                    mma_bf16(acc[mt][nt], al_[mt], bf[nt]);   // lo*hi
                }
        }
    }

    // epilogue
#pragma unroll
    for (int mt = 0; mt < MT; mt++)
#pragma unroll
        for (int nt = 0; nt < NT; nt++) {
            int row = m0 + wm0 + mt * 16 + (lane >> 2);
            int col = n0 + wn0 + nt * 8 + (lane & 3) * 2;
            float bx = 0.f, by = 0.f;
            if (bias) { bx = bias[col]; by = bias[col + 1]; }
            float2 v0 = make_float2(acc[mt][nt][0] * alpha + bx,
                                    acc[mt][nt][1] * alpha + by);
            float2 v1 = make_float2(acc[mt][nt][2] * alpha + bx,
                                    acc[mt][nt][3] * alpha + by);
            *(float2*)&C[(long)row * ldc + col] = v0;
            *(float2*)&C[(long)(row + 8) * ldc + col] = v1;
        }
}

// ---------------- masked softmax over rows of attn (in place) --------------
__global__ __launch_bounds__(256) void softmax_kernel(float* __restrict__ attn,
                                                      const unsigned char* __restrict__ mask) {
    __shared__ float s[HW_];
    __shared__ float red[8];
    __shared__ float bcast;
    long r = blockIdx.x;
    int n = (int)(r % N_);
    float* row = attn + r * (long)HW_;
    const unsigned char* mrow = mask + (long)n * HW_;
    int tid = threadIdx.x;
    int lane = tid & 31;
    int wid = tid >> 5;

    float mx = -INFINITY;
    for (int i = tid * 4; i < HW_; i += 1024) {
        float4 v = *(const float4*)(row + i);
        uchar4 mk = *(const uchar4*)(mrow + i);
        v.x = mk.x ? v.x : -INFINITY;
        v.y = mk.y ? v.y : -INFINITY;
        v.z = mk.z ? v.z : -INFINITY;
        v.w = mk.w ? v.w : -INFINITY;
        *(float4*)(s + i) = v;
        mx = fmaxf(mx, fmaxf(fmaxf(v.x, v.y), fmaxf(v.z, v.w)));
    }
#pragma unroll
    for (int o = 16; o; o >>= 1) mx = fmaxf(mx, __shfl_xor_sync(0xffffffffu, mx, o));
    if (lane == 0) red[wid] = mx;
    __syncthreads();
    if (tid == 0) {
        float m = red[0];
#pragma unroll
        for (int i = 1; i < 8; i++) m = fmaxf(m, red[i]);
        bcast = m;
    }
    __syncthreads();
    mx = bcast;

    float sum = 0.0f;
    for (int i = tid * 4; i < HW_; i += 1024) {
        float4 v = *(float4*)(s + i);
        v.x = __expf(v.x - mx);
        v.y = __expf(v.y - mx);
        v.z = __expf(v.z - mx);
        v.w = __expf(v.w - mx);
        *(float4*)(s + i) = v;
        sum += v.x + v.y + v.z + v.w;
    }
#pragma unroll
    for (int o = 16; o; o >>= 1) sum += __shfl_xor_sync(0xffffffffu, sum, o);
    __syncthreads();
    if (lane == 0) red[wid] = sum;
    __syncthreads();
    if (tid == 0) {
        float m = 0.f;
#pragma unroll
        for (int i = 0; i < 8; i++) m += red[i];
        bcast = 1.0f / m;
    }
    __syncthreads();
    float inv = bcast;
    for (int i = tid * 4; i < HW_; i += 1024) {
        float4 v = *(float4*)(s + i);
        v.x *= inv; v.y *= inv; v.z *= inv; v.w *= inv;
        *(float4*)(row + i) = v;
    }
}

// ---------------- launch ---------------------------------------------------
extern "C" void kernel_launch(void* const* d_in, const int* in_sizes, int n_in,
                              void* d_out, int out_size) {
    const float* query   = (const float*)d_in[0];
    const float* key     = (const float*)d_in[1];
    const float* value   = (const float*)d_in[2];
    const float* x_tilde = (const float*)d_in[3];
    const float* x_hat   = (const float*)d_in[4];
    const float* Wq = (const float*)d_in[5];
    const float* bq = (const float*)d_in[6];
    const float* Wk = (const float*)d_in[7];
    const float* bk = (const float*)d_in[8];
    const float* Wv = (const float*)d_in[9];
    const float* bv = (const float*)d_in[10];
    const float* Wo = (const float*)d_in[11];
    const float* bo = (const float*)d_in[12];

    float* out = (float*)d_out;
    float* attn = out + (size_t)B_ * N_ * D_;

    float *Qp, *Kp, *Vp, *Cp;
    unsigned char* Mp;
    cudaGetSymbolAddress((void**)&Qp, g_Q);
    cudaGetSymbolAddress((void**)&Kp, g_K);
    cudaGetSymbolAddress((void**)&Vp, g_V);
    cudaGetSymbolAddress((void**)&Cp, g_ctx);
    cudaGetSymbolAddress((void**)&Mp, g_mask);

    mask_kernel<<<(N_ * HW_ + 255) / 256, 256>>>(x_tilde, x_hat, Mp);

    // projections: C[M,512] = X @ W^T + b
    gemm_mma<128, 128, 32, 64, 32, true><<<dim3(D_ / 128, (B_ * N_) / 128, 1), 256>>>(
        query, Wq, bq, Qp, D_, D_, D_, D_, 0, 0, 0, 0, 0, 0, 1.0f);
    gemm_mma<128, 128, 32, 64, 32, true><<<dim3(D_ / 128, (B_ * HW_) / 128, 1), 256>>>(
        key, Wk, bk, Kp, D_, D_, D_, D_, 0, 0, 0, 0, 0, 0, 1.0f);
    gemm_mma<128, 128, 32, 64, 32, true><<<dim3(D_ / 128, (B_ * HW_) / 128, 1), 256>>>(
        value, Wv, bv, Vp, D_, D_, D_, D_, 0, 0, 0, 0, 0, 0, 1.0f);

    // scores: S[bh] = Q_bh @ K_bh^T * 0.125  -> raw scores into attn buffer
    gemm_mma<128, 128, 32, 64, 32, true><<<dim3(HW_ / 128, N_ / 128, B_ * H_), 256>>>(
        Qp, Kp, nullptr, attn, DK_, D_, D_, HW_,
        (long)N_ * D_, DK_, (long)HW_ * D_, DK_,
        (long)H_ * N_ * HW_, (long)N_ * HW_, 0.125f);

    // masked softmax in place over attn rows
    softmax_kernel<<<B_ * H_ * N_, 256>>>(attn, Mp);

    // ctx: ctx[bh] = P_bh @ V_bh
    gemm_mma<128, 64, 32, 64, 16, false><<<dim3(DK_ / 64, N_ / 128, B_ * H_), 256>>>(
        attn, Vp, nullptr, Cp, HW_, HW_, D_, D_,
        (long)H_ * N_ * HW_, (long)N_ * HW_, (long)HW_ * D_, DK_,
        (long)N_ * D_, DK_, 1.0f);

    // out projection
    gemm_mma<128, 128, 32, 64, 32, true><<<dim3(D_ / 128, (B_ * N_) / 128, 1), 256>>>(
        Cp, Wo, bo, out, D_, D_, D_, D_, 0, 0, 0, 0, 0, 0, 1.0f);
}

// round 3
// speedup vs baseline: 3.9495x; 2.0719x over previous
#include <cuda_runtime.h>
#include <cuda_bf16.h>
#include <math.h>
#include <stdint.h>

#define B_ 4
#define N_ 1024
#define HW_ 4096
#define D_ 512
#define H_ 8
#define DK_ 64

// ---------------- scratch (static device globals; no allocation) -----------
__device__ __nv_bfloat16 g_qh[B_ * N_ * D_],  g_ql[B_ * N_ * D_];
__device__ __nv_bfloat16 g_kh[B_ * HW_ * D_], g_kl[B_ * HW_ * D_];
__device__ __nv_bfloat16 g_vh[B_ * HW_ * D_], g_vl[B_ * HW_ * D_];
__device__ __nv_bfloat16 g_wqh[D_ * D_], g_wql[D_ * D_];
__device__ __nv_bfloat16 g_wkh[D_ * D_], g_wkl[D_ * D_];
__device__ __nv_bfloat16 g_wvh[D_ * D_], g_wvl[D_ * D_];
__device__ __nv_bfloat16 g_woh[D_ * D_], g_wol[D_ * D_];
__device__ __nv_bfloat16 g_Qh[B_ * N_ * D_],  g_Ql[B_ * N_ * D_];
__device__ __nv_bfloat16 g_Kh[B_ * HW_ * D_], g_Kl[B_ * HW_ * D_];
__device__ __nv_bfloat16 g_Vh[B_ * HW_ * D_], g_Vl[B_ * HW_ * D_];
__device__ __nv_bfloat16 g_ctxh[B_ * N_ * D_], g_ctxl[B_ * N_ * D_];
__device__ __nv_bfloat16 g_Ph[(size_t)B_ * H_ * N_ * HW_];
__device__ __nv_bfloat16 g_Pl[(size_t)B_ * H_ * N_ * HW_];
__device__ unsigned char g_mask[N_ * HW_];

// ---------------- helpers --------------------------------------------------
__device__ __forceinline__ uint32_t smem_u32(const void* p) {
    return (uint32_t)__cvta_generic_to_shared(p);
}
__device__ __forceinline__ void cp16(uint32_t s, const void* g) {
    asm volatile("cp.async.cg.shared.global [%0],[%1],16;" :: "r"(s), "l"(g));
}
__device__ __forceinline__ void cp_commit() {
    asm volatile("cp.async.commit_group;" ::: "memory");
}
template <int NN>
__device__ __forceinline__ void cp_wait() {
    asm volatile("cp.async.wait_group %0;" :: "n"(NN) : "memory");
}
__device__ __forceinline__ void ldsm4(uint32_t& r0, uint32_t& r1, uint32_t& r2,
                                      uint32_t& r3, uint32_t a) {
    asm volatile("ldmatrix.sync.aligned.m8n8.x4.shared.b16 {%0,%1,%2,%3},[%4];"
                 : "=r"(r0), "=r"(r1), "=r"(r2), "=r"(r3) : "r"(a));
}
__device__ __forceinline__ void ldsm4t(uint32_t& r0, uint32_t& r1, uint32_t& r2,
                                       uint32_t& r3, uint32_t a) {
    asm volatile("ldmatrix.sync.aligned.m8n8.x4.trans.shared.b16 {%0,%1,%2,%3},[%4];"
                 : "=r"(r0), "=r"(r1), "=r"(r2), "=r"(r3) : "r"(a));
}
__device__ __forceinline__ void mma_bf16(float* c, const uint32_t* a, const uint32_t* b) {
    asm volatile(
        "mma.sync.aligned.m16n8k16.row.col.f32.bf16.bf16.f32 "
        "{%0,%1,%2,%3},{%4,%5,%6,%7},{%8,%9},{%0,%1,%2,%3};"
        : "+f"(c[0]), "+f"(c[1]), "+f"(c[2]), "+f"(c[3])
        : "r"(a[0]), "r"(a[1]), "r"(a[2]), "r"(a[3]), "r"(b[0]), "r"(b[1]));
}
__device__ __forceinline__ void split2(float x, float y, uint32_t& hi, uint32_t& lo) {
    __nv_bfloat16 hx = __float2bfloat16(x);
    __nv_bfloat16 hy = __float2bfloat16(y);
    __nv_bfloat16 lx = __float2bfloat16(x - __bfloat162float(hx));
    __nv_bfloat16 ly = __float2bfloat16(y - __bfloat162float(hy));
    hi = (uint32_t)__bfloat16_as_ushort(hx) | ((uint32_t)__bfloat16_as_ushort(hy) << 16);
    lo = (uint32_t)__bfloat16_as_ushort(lx) | ((uint32_t)__bfloat16_as_ushort(ly) << 16);
}

// ---------------- split fp32 -> hi/lo bf16 ---------------------------------
__global__ void split_kernel(const float4* __restrict__ X, uint2* __restrict__ Xh,
                             uint2* __restrict__ Xl, int n4) {
    int i = blockIdx.x * blockDim.x + threadIdx.x;
    if (i >= n4) return;
    float4 v = X[i];
    uint32_t h0, l0, h1, l1;
    split2(v.x, v.y, h0, l0);
    split2(v.z, v.w, h1, l1);
    Xh[i] = make_uint2(h0, h1);
    Xl[i] = make_uint2(l0, l1);
}

// ---------------- mask precompute ------------------------------------------
__global__ void mask_kernel(const float* __restrict__ x_tilde,
                            const float* __restrict__ x_hat,
                            unsigned char* __restrict__ mask) {
    int idx = blockIdx.x * blockDim.x + threadIdx.x;
    if (idx >= N_ * HW_) return;
    int m = idx & (HW_ - 1);
    float dx = x_tilde[m * 2 + 0] - x_hat[(size_t)idx * 2 + 0];
    float dy = x_tilde[m * 2 + 1] - x_hat[(size_t)idx * 2 + 1];
    mask[idx] = (sqrtf(dx * dx + dy * dy) < 0.1f) ? 1 : 0;
}

// ---------------- pipelined split-bf16 MMA GEMM ----------------------------
// C = alpha * (A @ op(B)) + bias.  A,B given pre-split into hi/lo bf16.
// TRB: B stored [N,K]; else [K,N]. SPLITOUT: write hi/lo bf16, else fp32.
template <int BM, int BN, int BK, int WM, int WN, bool TRB, bool SPLITOUT>
__global__ void __launch_bounds__(256) gemm_bf16(
    const __nv_bfloat16* __restrict__ Agh, const __nv_bfloat16* __restrict__ Agl,
    const __nv_bfloat16* __restrict__ Bgh, const __nv_bfloat16* __restrict__ Bgl,
    const float* __restrict__ bias, float* __restrict__ C,
    __nv_bfloat16* __restrict__ Ch, __nv_bfloat16* __restrict__ Cl,
    int K, int lda, int ldb, int ldc,
    long sAb, long sAh0, long sBb, long sBh0, long sCb, long sCh0, float alpha) {
    constexpr int STAGES = 3;
    constexpr int SA = BK + 8;
    constexpr int SB = TRB ? (BK + 8) : (BN + 8);
    constexpr int BROWS = TRB ? BN : BK;
    constexpr int ASZ = BM * SA;
    constexpr int BSZ = BROWS * SB;
    constexpr int STRIDE = 2 * ASZ + 2 * BSZ;
    extern __shared__ __nv_bfloat16 smem[];

    int z = blockIdx.z;
    int zb = z >> 3, zh = z & 7;
    Agh += zb * sAb + zh * sAh0;
    Agl += zb * sAb + zh * sAh0;
    Bgh += zb * sBb + zh * sBh0;
    Bgl += zb * sBb + zh * sBh0;
    long coff = zb * sCb + zh * sCh0;

    int m0 = blockIdx.y * BM;
    int n0 = blockIdx.x * BN;
    int tid = threadIdx.x;
    int lane = tid & 31;
    int wid = tid >> 5;
    constexpr int WNC = BN / WN;
    int wm0 = (wid / WNC) * WM;
    int wn0 = (wid % WNC) * WN;
    constexpr int MT = WM / 16;
    constexpr int NT = WN / 8;
    constexpr int NTP = NT / 2;

    int nK = K / BK;
    uint32_t smem_b = smem_u32(smem);

    auto load_stage = [&](int kc, int s) {
        int k0 = kc * BK;
        uint32_t base = smem_b + s * STRIDE * 2;
        // A tiles (hi, lo)
        for (int i = tid; i < BM * (BK / 8); i += 256) {
            int r = i / (BK / 8);
            int c = (i % (BK / 8)) * 8;
            long go = (long)(m0 + r) * lda + k0 + c;
            uint32_t so = (uint32_t)(r * SA + c) * 2;
            cp16(base + so, Agh + go);
            cp16(base + ASZ * 2 + so, Agl + go);
        }
        // B tiles
        if constexpr (TRB) {
            for (int i = tid; i < BN * (BK / 8); i += 256) {
                int r = i / (BK / 8);
                int c = (i % (BK / 8)) * 8;
                long go = (long)(n0 + r) * ldb + k0 + c;
                uint32_t so = (uint32_t)(r * SB + c) * 2;
                cp16(base + 4 * ASZ + so, Bgh + go);  // note: 2*ASZ halfs = 4*ASZ bytes? no
            }
        }
    };
    // (lambda above replaced below; kept simple & correct in-line)

    // ---- explicit pipeline ----
    auto issue = [&](int kc) {
        int s = kc % STAGES;
        int k0 = kc * BK;
        uint32_t base = smem_b + (uint32_t)(s * STRIDE) * 2;  // bytes
        for (int i = tid; i < BM * (BK / 8); i += 256) {
            int r = i / (BK / 8);
            int c = (i % (BK / 8)) * 8;
            long go = (long)(m0 + r) * lda + k0 + c;
            uint32_t so = (uint32_t)(r * SA + c) * 2;
            cp16(base + so, Agh + go);
            cp16(base + (uint32_t)ASZ * 2 + so, Agl + go);
        }
        uint32_t bb = base + (uint32_t)(2 * ASZ) * 2;
        if constexpr (TRB) {
            for (int i = tid; i < BN * (BK / 8); i += 256) {
                int r = i / (BK / 8);
                int c = (i % (BK / 8)) * 8;
                long go = (long)(n0 + r) * ldb + k0 + c;
                uint32_t so = (uint32_t)(r * SB + c) * 2;
                cp16(bb + so, Bgh + go);
                cp16(bb + (uint32_t)BSZ * 2 + so, Bgl + go);
            }
        } else {
            for (int i = tid; i < BK * (BN / 8); i += 256) {
                int r = i / (BN / 8);
                int c = (i % (BN / 8)) * 8;
                long go = (long)(k0 + r) * ldb + n0 + c;
                uint32_t so = (uint32_t)(r * SB + c) * 2;
                cp16(bb + so, Bgh + go);
                cp16(bb + (uint32_t)BSZ * 2 + so, Bgl + go);
            }
        }
    };

    float acc[MT][NT][4];
#pragma unroll
    for (int i = 0; i < MT; i++)
#pragma unroll
        for (int j = 0; j < NT; j++)
#pragma unroll
            for (int q = 0; q < 4; q++) acc[i][j][q] = 0.0f;

    for (int s = 0; s < STAGES - 1; s++) {
        if (s < nK) issue(s);
        cp_commit();
    }

    for (int kc = 0; kc < nK; kc++) {
        int pf = kc + STAGES - 1;
        if (pf < nK) issue(pf);
        cp_commit();
        cp_wait<STAGES - 1>();
        __syncthreads();

        int s = kc % STAGES;
        const __nv_bfloat16* Ah_s = smem + s * STRIDE;
        const __nv_bfloat16* Al_s = Ah_s + ASZ;
        const __nv_bfloat16* Bh_s = Ah_s + 2 * ASZ;
        const __nv_bfloat16* Bl_s = Bh_s + BSZ;

#pragma unroll
        for (int ks = 0; ks < BK / 16; ks++) {
            uint32_t af[MT][4], al_[MT][4];
#pragma unroll
            for (int mt = 0; mt < MT; mt++) {
                int row = wm0 + mt * 16 + (lane & 15);
                int col = ks * 16 + (lane >> 4) * 8;
                ldsm4(af[mt][0], af[mt][1], af[mt][2], af[mt][3],
                      smem_u32(&Ah_s[row * SA + col]));
                ldsm4(al_[mt][0], al_[mt][1], al_[mt][2], al_[mt][3],
                      smem_u32(&Al_s[row * SA + col]));
            }
            uint32_t bfr[NT][2], blr[NT][2];
#pragma unroll
            for (int ntp = 0; ntp < NTP; ntp++) {
                int g = lane >> 3;
                int noff = (g >> 1) * 8;
                int koff = (g & 1) * 8;
                uint32_t r0, r1, r2, r3;
                if constexpr (TRB) {
                    int row = wn0 + ntp * 16 + noff + (lane & 7);
                    int col = ks * 16 + koff;
                    ldsm4(r0, r1, r2, r3, smem_u32(&Bh_s[row * SB + col]));
                    bfr[2 * ntp][0] = r0; bfr[2 * ntp][1] = r1;
                    bfr[2 * ntp + 1][0] = r2; bfr[2 * ntp + 1][1] = r3;
                    ldsm4(r0, r1, r2, r3, smem_u32(&Bl_s[row * SB + col]));
                    blr[2 * ntp][0] = r0; blr[2 * ntp][1] = r1;
                    blr[2 * ntp + 1][0] = r2; blr[2 * ntp + 1][1] = r3;
                } else {
                    int row = ks * 16 + koff + (lane & 7);
                    int col = wn0 + ntp * 16 + noff;
                    ldsm4t(r0, r1, r2, r3, smem_u32(&Bh_s[row * SB + col]));
                    bfr[2 * ntp][0] = r0; bfr[2 * ntp][1] = r1;
                    bfr[2 * ntp + 1][0] = r2; bfr[2 * ntp + 1][1] = r3;
                    ldsm4t(r0, r1, r2, r3, smem_u32(&Bl_s[row * SB + col]));
                    blr[2 * ntp][0] = r0; blr[2 * ntp][1] = r1;
                    blr[2 * ntp + 1][0] = r2; blr[2 * ntp + 1][1] = r3;
                }
            }
#pragma unroll
            for (int mt = 0; mt < MT; mt++)
#pragma unroll
                for (int nt = 0; nt < NT; nt++) {
                    mma_bf16(acc[mt][nt], af[mt], bfr[nt]);
                    mma_bf16(acc[mt][nt], af[mt], blr[nt]);
                    mma_bf16(acc[mt][nt], al_[mt], bfr[nt]);
                }
        }
        __syncthreads();
    }

    // ---- epilogue ----
#pragma unroll
    for (int mt = 0; mt < MT; mt++)
#pragma unroll
        for (int nt = 0; nt < NT; nt++) {
            int row = m0 + wm0 + mt * 16 + (lane >> 2);
            int col = n0 + wn0 + nt * 8 + (lane & 3) * 2;
            float bx = 0.f, by = 0.f;
            if (bias) { bx = bias[col]; by = bias[col + 1]; }
            float v0x = acc[mt][nt][0] * alpha + bx;
            float v0y = acc[mt][nt][1] * alpha + by;
            float v1x = acc[mt][nt][2] * alpha + bx;
            float v1y = acc[mt][nt][3] * alpha + by;
            if constexpr (SPLITOUT) {
                uint32_t h, l;
                split2(v0x, v0y, h, l);
                *(uint32_t*)&Ch[coff + (long)row * ldc + col] = h;
                *(uint32_t*)&Cl[coff + (long)row * ldc + col] = l;
                split2(v1x, v1y, h, l);
                *(uint32_t*)&Ch[coff + (long)(row + 8) * ldc + col] = h;
                *(uint32_t*)&Cl[coff + (long)(row + 8) * ldc + col] = l;
            } else {
                *(float2*)&C[coff + (long)row * ldc + col] = make_float2(v0x, v0y);
                *(float2*)&C[coff + (long)(row + 8) * ldc + col] = make_float2(v1x, v1y);
            }
        }
}

// ---------------- masked softmax + P split ---------------------------------
__global__ __launch_bounds__(256) void softmax_kernel(
    float* __restrict__ attn, const unsigned char* __restrict__ mask,
    __nv_bfloat16* __restrict__ Ph, __nv_bfloat16* __restrict__ Pl) {
    __shared__ float s[HW_];
    __shared__ float red[8];
    __shared__ float bcast;
    long r = blockIdx.x;
    int n = (int)(r % N_);
    float* row = attn + r * (long)HW_;
    __nv_bfloat16* ph = Ph + r * (long)HW_;
    __nv_bfloat16* pl = Pl + r * (long)HW_;
    const unsigned char* mrow = mask + (long)n * HW_;
    int tid = threadIdx.x;
    int lane = tid & 31;
    int wid = tid >> 5;

    float mx = -INFINITY;
    for (int i = tid * 4; i < HW_; i += 1024) {
        float4 v = *(const float4*)(row + i);
        uchar4 mk = *(const uchar4*)(mrow + i);
        v.x = mk.x ? v.x : -INFINITY;
        v.y = mk.y ? v.y : -INFINITY;
        v.z = mk.z ? v.z : -INFINITY;
        v.w = mk.w ? v.w : -INFINITY;
        *(float4*)(s + i) = v;
        mx = fmaxf(mx, fmaxf(fmaxf(v.x, v.y), fmaxf(v.z, v.w)));
    }
#pragma unroll
    for (int o = 16; o; o >>= 1) mx = fmaxf(mx, __shfl_xor_sync(0xffffffffu, mx, o));
    if (lane == 0) red[wid] = mx;
    __syncthreads();
    if (tid == 0) {
        float m = red[0];
#pragma unroll
        for (int i = 1; i < 8; i++) m = fmaxf(m, red[i]);
        bcast = m;
    }
    __syncthreads();
    mx = bcast;

    float sum = 0.0f;
    for (int i = tid * 4; i < HW_; i += 1024) {
        float4 v = *(float4*)(s + i);
        v.x = __expf(v.x - mx);
        v.y = __expf(v.y - mx);
        v.z = __expf(v.z - mx);
        v.w = __expf(v.w - mx);
        *(float4*)(s + i) = v;
        sum += v.x + v.y + v.z + v.w;
    }
#pragma unroll
    for (int o = 16; o; o >>= 1) sum += __shfl_xor_sync(0xffffffffu, sum, o);
    __syncthreads();
    if (lane == 0) red[wid] = sum;
    __syncthreads();
    if (tid == 0) {
        float m = 0.f;
#pragma unroll
        for (int i = 0; i < 8; i++) m += red[i];
        bcast = 1.0f / m;
    }
    __syncthreads();
    float inv = bcast;
    for (int i = tid * 4; i < HW_; i += 1024) {
        float4 v = *(float4*)(s + i);
        v.x *= inv; v.y *= inv; v.z *= inv; v.w *= inv;
        *(float4*)(row + i) = v;
        uint32_t h0, l0, h1, l1;
        split2(v.x, v.y, h0, l0);
        split2(v.z, v.w, h1, l1);
        *(uint2*)&ph[i] = make_uint2(h0, h1);
        *(uint2*)&pl[i] = make_uint2(l0, l1);
    }
}

// ---------------- launch ---------------------------------------------------
extern "C" void kernel_launch(void* const* d_in, const int* in_sizes, int n_in,
                              void* d_out, int out_size) {
    const float* query   = (const float*)d_in[0];
    const float* key     = (const float*)d_in[1];
    const float* value   = (const float*)d_in[2];
    const float* x_tilde = (const float*)d_in[3];
    const float* x_hat   = (const float*)d_in[4];
    const float* Wq = (const float*)d_in[5];
    const float* bq = (const float*)d_in[6];
    const float* Wk = (const float*)d_in[7];
    const float* bk = (const float*)d_in[8];
    const float* Wv = (const float*)d_in[9];
    const float* bv = (const float*)d_in[10];
    const float* Wo = (const float*)d_in[11];
    const float* bo = (const float*)d_in[12];

    float* out = (float*)d_out;
    float* attn = out + (size_t)B_ * N_ * D_;

    __nv_bfloat16 *qh, *ql, *kh, *kl, *vh, *vl;
    __nv_bfloat16 *wqh, *wql, *wkh, *wkl, *wvh, *wvl, *woh, *wol;
    __nv_bfloat16 *Qh, *Ql, *Kh, *Kl, *Vh, *Vl, *ch, *cl, *Ph, *Pl;
    unsigned char* Mp;
    cudaGetSymbolAddress((void**)&qh, g_qh);   cudaGetSymbolAddress((void**)&ql, g_ql);
    cudaGetSymbolAddress((void**)&kh, g_kh);   cudaGetSymbolAddress((void**)&kl, g_kl);
    cudaGetSymbolAddress((void**)&vh, g_vh);   cudaGetSymbolAddress((void**)&vl, g_vl);
    cudaGetSymbolAddress((void**)&wqh, g_wqh); cudaGetSymbolAddress((void**)&wql, g_wql);
    cudaGetSymbolAddress((void**)&wkh, g_wkh); cudaGetSymbolAddress((void**)&wkl, g_wkl);
    cudaGetSymbolAddress((void**)&wvh, g_wvh); cudaGetSymbolAddress((void**)&wvl, g_wvl);
    cudaGetSymbolAddress((void**)&woh, g_woh); cudaGetSymbolAddress((void**)&wol, g_wol);
    cudaGetSymbolAddress((void**)&Qh, g_Qh);   cudaGetSymbolAddress((void**)&Ql, g_Ql);
    cudaGetSymbolAddress((void**)&Kh, g_Kh);   cudaGetSymbolAddress((void**)&Kl, g_Kl);
    cudaGetSymbolAddress((void**)&Vh, g_Vh);   cudaGetSymbolAddress((void**)&Vl, g_Vl);
    cudaGetSymbolAddress((void**)&ch, g_ctxh); cudaGetSymbolAddress((void**)&cl, g_ctxl);
    cudaGetSymbolAddress((void**)&Ph, g_Ph);   cudaGetSymbolAddress((void**)&Pl, g_Pl);
    cudaGetSymbolAddress((void**)&Mp, g_mask);

    mask_kernel<<<(N_ * HW_ + 255) / 256, 256>>>(x_tilde, x_hat, Mp);

    // input / weight splits
    split_kernel<<<(B_ * N_ * D_ / 4 + 255) / 256, 256>>>(
        (const float4*)query, (uint2*)qh, (uint2*)ql, B_ * N_ * D_ / 4);
    split_kernel<<<(B_ * HW_ * D_ / 4 + 255) / 256, 256>>>(
        (const float4*)key, (uint2*)kh, (uint2*)kl, B_ * HW_ * D_ / 4);
    split_kernel<<<(B_ * HW_ * D_ / 4 + 255) / 256, 256>>>(
        (const float4*)value, (uint2*)vh, (uint2*)vl, B_ * HW_ * D_ / 4);
    split_kernel<<<(D_ * D_ / 4 + 255) / 256, 256>>>(
        (const float4*)Wq, (uint2*)wqh, (uint2*)wql, D_ * D_ / 4);
    split_kernel<<<(D_ * D_ / 4 + 255) / 256, 256>>>(
        (const float4*)Wk, (uint2*)wkh, (uint2*)wkl, D_ * D_ / 4);
    split_kernel<<<(D_ * D_ / 4 + 255) / 256, 256>>>(
        (const float4*)Wv, (uint2*)wvh, (uint2*)wvl, D_ * D_ / 4);
    split_kernel<<<(D_ * D_ / 4 + 255) / 256, 256>>>(
        (const float4*)Wo, (uint2*)woh, (uint2*)wol, D_ * D_ / 4);

    constexpr int SMEM_BIG = 3 * (2 * 128 * 40 + 2 * 128 * 40) * 2;  // 122880
    constexpr int SMEM_CTX = 3 * (2 * 64 * 40 + 2 * 32 * 72) * 2;    // 58368

    auto* kProj = gemm_bf16<128, 128, 32, 64, 32, true, true>;
    auto* kF32  = gemm_bf16<128, 128, 32, 64, 32, true, false>;
    auto* kCtx  = gemm_bf16<64, 64, 32, 32, 16, false, true>;
    cudaFuncSetAttribute(kProj, cudaFuncAttributeMaxDynamicSharedMemorySize, SMEM_BIG);
    cudaFuncSetAttribute(kF32, cudaFuncAttributeMaxDynamicSharedMemorySize, SMEM_BIG);
    cudaFuncSetAttribute(kCtx, cudaFuncAttributeMaxDynamicSharedMemorySize, SMEM_CTX);

    // projections -> split bf16 outputs
    kProj<<<dim3(4, 32, 1), 256, SMEM_BIG>>>(qh, ql, wqh, wql, bq, nullptr, Qh, Ql,
                                             D_, D_, D_, D_, 0, 0, 0, 0, 0, 0, 1.0f);
    kProj<<<dim3(4, 128, 1), 256, SMEM_BIG>>>(kh, kl, wkh, wkl, bk, nullptr, Kh, Kl,
                                              D_, D_, D_, D_, 0, 0, 0, 0, 0, 0, 1.0f);
    kProj<<<dim3(4, 128, 1), 256, SMEM_BIG>>>(vh, vl, wvh, wvl, bv, nullptr, Vh, Vl,
                                              D_, D_, D_, D_, 0, 0, 0, 0, 0, 0, 1.0f);

    // scores -> fp32 raw into attn buffer
    kF32<<<dim3(32, 8, 32), 256, SMEM_BIG>>>(
        Qh, Ql, Kh, Kl, nullptr, attn, nullptr, nullptr,
        DK_, D_, D_, HW_,
        (long)N_ * D_, DK_, (long)HW_ * D_, DK_,
        (long)H_ * N_ * HW_, (long)N_ * HW_, 0.125f);

    softmax_kernel<<<B_ * H_ * N_, 256>>>(attn, Mp, Ph, Pl);

    // ctx = P @ V -> split bf16
    kCtx<<<dim3(1, 16, 32), 256, SMEM_CTX>>>(
        Ph, Pl, Vh, Vl, nullptr, nullptr, ch, cl,
        HW_, HW_, D_, D_,
        (long)H_ * N_ * HW_, (long)N_ * HW_, (long)HW_ * D_, DK_,
        (long)N_ * D_, DK_, 1.0f);

    // out projection -> fp32
    kF32<<<dim3(4, 32, 1), 256, SMEM_BIG>>>(
        ch, cl, woh, wol, bo, out, nullptr, nullptr,
        D_, D_, D_, D_, 0, 0, 0, 0, 0, 0, 1.0f);
}